// round 2
// baseline (speedup 1.0000x reference)
#include <cuda_runtime.h>
#include <cstdint>
#include <cstddef>

// Fixed problem sizes
#define NN 100000          // nodes
#define NR 8               // relations
#define DD 128             // hidden dim
#define EE 800000          // edges
#define NW 9               // 8 relations + root
#define NTILES 782         // ceil(NN/128)
#define XS_STRIDE 132      // padded smem row stride (floats) -> conflict-free frags

// ---------------------------------------------------------------------------
// Device scratch (no allocation allowed)
// ---------------------------------------------------------------------------
__device__ float g_H[(size_t)NR * NN * DD];   // 409.6 MB: H[r][node][dim]
__device__ float g_x1[(size_t)NN * DD];       // 51.2 MB layer-1 pre-activation
__device__ float g_Wt[NW * DD * DD];          // Wt[w][o][i], tf32-rounded
__device__ int   g_cnt[NN * NR];
__device__ float g_inv[NN * NR];

// ---------------------------------------------------------------------------
// helpers
// ---------------------------------------------------------------------------
__device__ __forceinline__ uint32_t f2tf32(float x) {
    uint32_t u;
    asm("cvt.rna.tf32.f32 %0, %1;" : "=r"(u) : "f"(x));
    return u;
}

__device__ __forceinline__ void mma_tf32(float* d, const uint32_t* a, const uint32_t* b) {
    asm volatile(
        "mma.sync.aligned.m16n8k8.row.col.f32.tf32.tf32.f32 "
        "{%0,%1,%2,%3}, {%4,%5,%6,%7}, {%8,%9}, {%0,%1,%2,%3};"
        : "+f"(d[0]), "+f"(d[1]), "+f"(d[2]), "+f"(d[3])
        : "r"(a[0]), "r"(a[1]), "r"(a[2]), "r"(a[3]), "r"(b[0]), "r"(b[1]));
}

__device__ __forceinline__ void cp_async16(uint32_t smem_addr, const void* gptr) {
    asm volatile("cp.async.cg.shared.global [%0], [%1], 16;" :: "r"(smem_addr), "l"(gptr));
}

// ---------------------------------------------------------------------------
// small kernels
// ---------------------------------------------------------------------------
__global__ void zero_cnt_kernel() {
    int i = blockIdx.x * blockDim.x + threadIdx.x;
    if (i < NN * NR) g_cnt[i] = 0;
}

__global__ void count_kernel(const int* __restrict__ ei, const int* __restrict__ et) {
    int e = blockIdx.x * blockDim.x + threadIdx.x;
    if (e < EE) atomicAdd(&g_cnt[ei[EE + e] * NR + et[e]], 1);
}

__global__ void inv_kernel() {
    int i = blockIdx.x * blockDim.x + threadIdx.x;
    if (i < NN * NR) g_inv[i] = 1.0f / fmaxf((float)g_cnt[i], 1.0f);
}

// Wt[w][o][i] = sum_b comp[w][b]*basis[b][i][o]  (w<8) ; root[i][o] (w==8)
__global__ void prep_wt_kernel(const float* __restrict__ comp,
                               const float* __restrict__ basis,
                               const float* __restrict__ root) {
    int idx = blockIdx.x * blockDim.x + threadIdx.x;
    if (idx >= NW * DD * DD) return;
    int w = idx >> 14;
    int rem = idx & 16383;
    int o = rem >> 7, i = rem & 127;
    float v;
    if (w < NR) {
        v = 0.f;
#pragma unroll
        for (int b = 0; b < 8; b++)
            v += comp[w * 8 + b] * basis[((size_t)b * DD + i) * DD + o];
    } else {
        v = root[i * DD + o];
    }
    g_Wt[idx] = __uint_as_float(f2tf32(v));
}

// ---------------------------------------------------------------------------
// GEMM: per 128-row node tile compute H[w] = X @ W_w (w=0..7) and
// out_base = X @ root + bias, via mma.sync tf32; cp.async double-buffers W.
// ---------------------------------------------------------------------------
#define SMF_X   0
#define SMF_W   (DD * XS_STRIDE)
#define SMF_B   (3 * DD * XS_STRIDE)
#define SM_FLOATS (3 * DD * XS_STRIDE + DD)

__global__ void __launch_bounds__(256, 1)
gemm_kernel(const float* __restrict__ X, const float* __restrict__ bias,
            int relu_in, float* __restrict__ outb) {
    extern __shared__ float sm[];
    float* Xs = sm + SMF_X;
    float* Ws = sm + SMF_W;           // two buffers of DD*XS_STRIDE
    float* bs = sm + SMF_B;

    const int tid = threadIdx.x;
    const int row0 = blockIdx.x * 128;

    if (tid < 128) bs[tid] = bias[tid];

    // stage X tile (with optional ReLU), converted to tf32 (rna)
    for (int c = tid; c < 128 * 32; c += 256) {
        int r = c >> 5, cc = c & 31;
        int g = row0 + r;
        float4 v = make_float4(0.f, 0.f, 0.f, 0.f);
        if (g < NN) v = *((const float4*)(X + (size_t)g * DD) + cc);
        if (relu_in) {
            v.x = fmaxf(v.x, 0.f); v.y = fmaxf(v.y, 0.f);
            v.z = fmaxf(v.z, 0.f); v.w = fmaxf(v.w, 0.f);
        }
        float4 t;
        t.x = __uint_as_float(f2tf32(v.x));
        t.y = __uint_as_float(f2tf32(v.y));
        t.z = __uint_as_float(f2tf32(v.z));
        t.w = __uint_as_float(f2tf32(v.w));
        *(float4*)(Xs + r * XS_STRIDE + cc * 4) = t;
    }

    // prefetch W[0] into buffer 0
    for (int c = tid; c < 128 * 32; c += 256) {
        int o = c >> 5, cc = c & 31;
        uint32_t sa = (uint32_t)__cvta_generic_to_shared(Ws + o * XS_STRIDE + cc * 4);
        cp_async16(sa, g_Wt + o * DD + cc * 4);
    }
    asm volatile("cp.async.commit_group;" ::: "memory");

    const int wid = tid >> 5, lane = tid & 31;
    const int m0 = (wid >> 1) * 32, n0 = (wid & 1) * 64;
    const int gq = lane >> 2, tg = lane & 3;

    const float* Xb = Xs + (m0 + gq) * XS_STRIDE + tg;

    for (int w = 0; w < NW; w++) {
        asm volatile("cp.async.wait_group 0;" ::: "memory");
        __syncthreads();

        float* Wcur = Ws + (w & 1) * (DD * XS_STRIDE);
        if (w + 1 < NW) {
            float* dstb = Ws + ((w + 1) & 1) * (DD * XS_STRIDE);
            const float* src = g_Wt + (size_t)(w + 1) * DD * DD;
            for (int c = tid; c < 128 * 32; c += 256) {
                int o = c >> 5, cc = c & 31;
                uint32_t sa = (uint32_t)__cvta_generic_to_shared(dstb + o * XS_STRIDE + cc * 4);
                cp_async16(sa, src + o * DD + cc * 4);
            }
            asm volatile("cp.async.commit_group;" ::: "memory");
        }

        float acc[2][8][4];
#pragma unroll
        for (int mi = 0; mi < 2; mi++)
#pragma unroll
            for (int ni = 0; ni < 8; ni++)
#pragma unroll
                for (int j = 0; j < 4; j++) acc[mi][ni][j] = 0.f;

        const float* Wb = Wcur + (n0 + gq) * XS_STRIDE + tg;

#pragma unroll
        for (int k0 = 0; k0 < 128; k0 += 8) {
            uint32_t a[2][4];
#pragma unroll
            for (int mi = 0; mi < 2; mi++) {
                const float* p = Xb + mi * 16 * XS_STRIDE + k0;
                a[mi][0] = __float_as_uint(p[0]);
                a[mi][1] = __float_as_uint(p[8 * XS_STRIDE]);
                a[mi][2] = __float_as_uint(p[4]);
                a[mi][3] = __float_as_uint(p[8 * XS_STRIDE + 4]);
            }
            uint32_t b[8][2];
#pragma unroll
            for (int ni = 0; ni < 8; ni++) {
                const float* p = Wb + ni * 8 * XS_STRIDE + k0;
                b[ni][0] = __float_as_uint(p[0]);
                b[ni][1] = __float_as_uint(p[4]);
            }
#pragma unroll
            for (int mi = 0; mi < 2; mi++)
#pragma unroll
                for (int ni = 0; ni < 8; ni++)
                    mma_tf32(acc[mi][ni], a[mi], b[ni]);
        }

        // epilogue: relations -> g_H, root -> outb (+bias)
        float* dst = (w < NR) ? (g_H + ((size_t)w * NN + row0) * DD)
                              : (outb + (size_t)row0 * DD);
#pragma unroll
        for (int mi = 0; mi < 2; mi++) {
#pragma unroll
            for (int part = 0; part < 2; part++) {
                int row = m0 + mi * 16 + gq + part * 8;
                if (row0 + row < NN) {
                    float* dr = dst + (size_t)row * DD;
#pragma unroll
                    for (int ni = 0; ni < 8; ni++) {
                        int col = n0 + ni * 8 + 2 * tg;
                        float2 v;
                        v.x = acc[mi][ni][part * 2 + 0];
                        v.y = acc[mi][ni][part * 2 + 1];
                        if (w == NR) { v.x += bs[col]; v.y += bs[col + 1]; }
                        *(float2*)(dr + col) = v;
                    }
                }
            }
        }
        __syncthreads();   // done with Wcur before it becomes a prefetch dst
    }
}

// ---------------------------------------------------------------------------
// Scatter: out[dst] += H[t][src] * inv(dst,t); one warp per edge, v4 reductions
// ---------------------------------------------------------------------------
__global__ void __launch_bounds__(256)
scatter_kernel(const int* __restrict__ ei, const int* __restrict__ et,
               float* __restrict__ out) {
    int e = blockIdx.x * 8 + (threadIdx.x >> 5);
    int lane = threadIdx.x & 31;
    if (e >= EE) return;
    int src = 0, dst = 0, t = 0;
    if (lane == 0) { src = ei[e]; dst = ei[EE + e]; t = et[e]; }
    src = __shfl_sync(0xffffffffu, src, 0);
    dst = __shfl_sync(0xffffffffu, dst, 0);
    t   = __shfl_sync(0xffffffffu, t, 0);
    float inv = __ldg(&g_inv[dst * NR + t]);

    float4 v = __ldg((const float4*)(g_H + ((size_t)t * NN + src) * DD) + lane);
    float* p = out + (size_t)dst * DD + lane * 4;
    asm volatile("red.global.add.v4.f32 [%0], {%1, %2, %3, %4};"
                 :: "l"(p), "f"(v.x * inv), "f"(v.y * inv), "f"(v.z * inv), "f"(v.w * inv)
                 : "memory");
}

// ---------------------------------------------------------------------------
extern "C" void kernel_launch(void* const* d_in, const int* in_sizes, int n_in,
                              void* d_out, int out_size) {
    const int*   ei     = (const int*)d_in[0];
    const int*   et     = (const int*)d_in[1];
    const float* emb    = (const float*)d_in[2];
    const float* basis1 = (const float*)d_in[3];
    const float* comp1  = (const float*)d_in[4];
    const float* root1  = (const float*)d_in[5];
    const float* bias1  = (const float*)d_in[6];
    const float* basis2 = (const float*)d_in[7];
    const float* comp2  = (const float*)d_in[8];
    const float* root2  = (const float*)d_in[9];
    const float* bias2  = (const float*)d_in[10];
    float* out = (float*)d_out;

    cudaFuncSetAttribute(gemm_kernel, cudaFuncAttributeMaxDynamicSharedMemorySize,
                         SM_FLOATS * 4);

    float* x1;
    cudaGetSymbolAddress((void**)&x1, g_x1);

    zero_cnt_kernel<<<3125, 256>>>();
    count_kernel<<<3125, 256>>>(ei, et);
    inv_kernel<<<3125, 256>>>();

    // layer 1: emb -> g_x1 (pre-activation; ReLU fused into layer-2 staging)
    prep_wt_kernel<<<576, 256>>>(comp1, basis1, root1);
    gemm_kernel<<<NTILES, 256, SM_FLOATS * 4>>>(emb, bias1, 0, x1);
    scatter_kernel<<<100000, 256>>>(ei, et, x1);

    // layer 2: relu(g_x1) -> d_out
    prep_wt_kernel<<<576, 256>>>(comp2, basis2, root2);
    gemm_kernel<<<NTILES, 256, SM_FLOATS * 4>>>(x1, bias2, 1, out);
    scatter_kernel<<<100000, 256>>>(ei, et, out);
}

// round 3
// speedup vs baseline: 1.8340x; 1.8340x over previous
#include <cuda_runtime.h>
#include <cuda_fp16.h>
#include <cstdint>
#include <cstddef>

// Fixed problem sizes
#define NN 100000          // nodes
#define NR 8               // relations
#define DD 128             // hidden dim
#define EE 800000          // edges
#define NW 9               // 8 relations + root
#define NTILES 782         // ceil(NN/128)
#define NBLK 391           // ceil(NN/256) for scans
#define XSH 136            // smem stride in halfs (272B -> ldmatrix conflict-free)

// ---------------------------------------------------------------------------
// Device scratch (allocation-free rule)
// ---------------------------------------------------------------------------
__device__ __half g_H[(size_t)NR * NN * DD];     // 204.8 MB: H[r][node][dim] fp16
__device__ float  g_x1[(size_t)NN * DD];         // 51.2 MB layer-1 pre-activation
__device__ __half g_Wh[NW * DD * DD];            // W[w][k][o]  (k-major!)
__device__ int    g_cnt[NN * NR];                // per (dst,rel) in-degree
__device__ float  g_inv[NN * NR];
__device__ int    g_dcnt[NN];                    // per-dst total degree
__device__ int    g_rowptr[NN + 1];              // CSR row pointers (by dst)
__device__ int    g_dpos[NN];                    // fill cursors
__device__ int    g_bsum[NBLK];                  // scan block sums
__device__ int    g_ehidx[EE];                   // t*NN + src, sorted by dst
__device__ float  g_escale[EE];                  // 1/cnt(dst,t), sorted by dst

// ---------------------------------------------------------------------------
// PTX helpers
// ---------------------------------------------------------------------------
__device__ __forceinline__ void ldsm4(uint32_t* r, uint32_t addr) {
    asm volatile("ldmatrix.sync.aligned.m8n8.x4.shared.b16 {%0,%1,%2,%3}, [%4];"
                 : "=r"(r[0]), "=r"(r[1]), "=r"(r[2]), "=r"(r[3]) : "r"(addr));
}
__device__ __forceinline__ void ldsm4t(uint32_t* r, uint32_t addr) {
    asm volatile("ldmatrix.sync.aligned.m8n8.x4.trans.shared.b16 {%0,%1,%2,%3}, [%4];"
                 : "=r"(r[0]), "=r"(r[1]), "=r"(r[2]), "=r"(r[3]) : "r"(addr));
}
__device__ __forceinline__ void mma_f16(float* d, const uint32_t* a, uint32_t b0, uint32_t b1) {
    asm volatile(
        "mma.sync.aligned.m16n8k16.row.col.f32.f16.f16.f32 "
        "{%0,%1,%2,%3}, {%4,%5,%6,%7}, {%8,%9}, {%0,%1,%2,%3};"
        : "+f"(d[0]), "+f"(d[1]), "+f"(d[2]), "+f"(d[3])
        : "r"(a[0]), "r"(a[1]), "r"(a[2]), "r"(a[3]), "r"(b0), "r"(b1));
}
__device__ __forceinline__ void cp_async16(uint32_t smem_addr, const void* gptr) {
    asm volatile("cp.async.cg.shared.global [%0], [%1], 16;" :: "r"(smem_addr), "l"(gptr));
}

// ---------------------------------------------------------------------------
// graph preprocessing (built once, reused for both layers)
// ---------------------------------------------------------------------------
__global__ void zero_counts_kernel() {
    int i = blockIdx.x * blockDim.x + threadIdx.x;
    if (i < NN * NR) g_cnt[i] = 0;
    if (i < NN) g_dcnt[i] = 0;
}

__global__ void count_kernel(const int* __restrict__ ei, const int* __restrict__ et) {
    int e = blockIdx.x * blockDim.x + threadIdx.x;
    if (e < EE) {
        int dst = ei[EE + e], t = et[e];
        atomicAdd(&g_cnt[dst * NR + t], 1);
        atomicAdd(&g_dcnt[dst], 1);
    }
}

__global__ void inv_kernel() {
    int i = blockIdx.x * blockDim.x + threadIdx.x;
    if (i < NN * NR) g_inv[i] = 1.0f / fmaxf((float)g_cnt[i], 1.0f);
}

__global__ void scan1_kernel() {   // block sums of g_dcnt
    __shared__ int sc[256];
    int i = blockIdx.x * 256 + threadIdx.x;
    sc[threadIdx.x] = (i < NN) ? g_dcnt[i] : 0;
    __syncthreads();
    for (int off = 128; off > 0; off >>= 1) {
        if (threadIdx.x < off) sc[threadIdx.x] += sc[threadIdx.x + off];
        __syncthreads();
    }
    if (threadIdx.x == 0) g_bsum[blockIdx.x] = sc[0];
}

__global__ void scan2_kernel() {   // serial exclusive prefix over block sums
    int run = 0;
    for (int b = 0; b < NBLK; b++) { int t = g_bsum[b]; g_bsum[b] = run; run += t; }
    g_rowptr[NN] = run;            // == EE
}

__global__ void scan3_kernel() {   // rowptr = global exclusive prefix; init cursors
    __shared__ int sc[256];
    int i = blockIdx.x * 256 + threadIdx.x;
    int c = (i < NN) ? g_dcnt[i] : 0;
    sc[threadIdx.x] = c;
    __syncthreads();
    for (int off = 1; off < 256; off <<= 1) {
        int v = (threadIdx.x >= off) ? sc[threadIdx.x - off] : 0;
        __syncthreads();
        sc[threadIdx.x] += v;
        __syncthreads();
    }
    if (i < NN) {
        int rp = g_bsum[blockIdx.x] + sc[threadIdx.x] - c;
        g_rowptr[i] = rp;
        g_dpos[i] = rp;
    }
}

__global__ void fill_kernel(const int* __restrict__ ei, const int* __restrict__ et) {
    int e = blockIdx.x * blockDim.x + threadIdx.x;
    if (e >= EE) return;
    int src = ei[e], dst = ei[EE + e], t = et[e];
    int pos = atomicAdd(&g_dpos[dst], 1);
    g_ehidx[pos] = t * NN + src;
    g_escale[pos] = g_inv[dst * NR + t];
}

// ---------------------------------------------------------------------------
// weight prep: g_Wh[w][k][o] fp16 (k-major)
// ---------------------------------------------------------------------------
__global__ void prep_wh_kernel(const float* __restrict__ comp,
                               const float* __restrict__ basis,
                               const float* __restrict__ root) {
    int idx = blockIdx.x * blockDim.x + threadIdx.x;
    if (idx >= NW * DD * DD) return;
    int w = idx >> 14;
    int rem = idx & 16383;
    int k = rem >> 7, o = rem & 127;
    float v;
    if (w < NR) {
        v = 0.f;
#pragma unroll
        for (int b = 0; b < 8; b++)
            v += comp[w * 8 + b] * basis[((size_t)b * DD + k) * DD + o];
    } else {
        v = root[k * DD + o];
    }
    g_Wh[idx] = __float2half_rn(v);
}

// ---------------------------------------------------------------------------
// GEMM: per 128-node tile, H[w] = X @ W_w (w=0..7, fp16 out) and
// out = X @ root + bias (fp32). fp16 mma m16n8k16 + ldmatrix, cp.async W.
// ---------------------------------------------------------------------------
#define SMEMB (3 * 128 * XSH * 2 + 512)

__global__ void __launch_bounds__(256)
gemm_h_kernel(const float* __restrict__ X, const float* __restrict__ bias,
              int relu_in, float* __restrict__ outb) {
    extern __shared__ __half smh[];
    __half* Xs = smh;                      // [128][XSH]
    __half* Ws = smh + 128 * XSH;          // 2 buffers [128][XSH]
    float* bs = (float*)(smh + 3 * 128 * XSH);

    const int tid = threadIdx.x;
    const int row0 = blockIdx.x * 128;
    if (tid < 128) bs[tid] = bias[tid];

    // stage X tile as fp16 (optional ReLU)
    for (int c = tid; c < 128 * 32; c += 256) {
        int r = c >> 5, cc = c & 31;
        int g = row0 + r;
        float4 v = make_float4(0.f, 0.f, 0.f, 0.f);
        if (g < NN) v = *((const float4*)(X + (size_t)g * DD) + cc);
        if (relu_in) {
            v.x = fmaxf(v.x, 0.f); v.y = fmaxf(v.y, 0.f);
            v.z = fmaxf(v.z, 0.f); v.w = fmaxf(v.w, 0.f);
        }
        __half2 h0 = __floats2half2_rn(v.x, v.y);
        __half2 h1 = __floats2half2_rn(v.z, v.w);
        __half2* p = (__half2*)(Xs + r * XSH + cc * 4);
        p[0] = h0; p[1] = h1;
    }

    // prefetch W[0] (k-major) into buffer 0 via cp.async (16B = 8 halfs)
    for (int c = tid; c < 2048; c += 256) {
        int k = c >> 4, c8 = c & 15;
        uint32_t sa = (uint32_t)__cvta_generic_to_shared(Ws + k * XSH + c8 * 8);
        cp_async16(sa, g_Wh + k * DD + c8 * 8);
    }
    asm volatile("cp.async.commit_group;" ::: "memory");

    const int wid = tid >> 5, lane = tid & 31;
    const int m0 = (wid >> 1) * 32, n0 = (wid & 1) * 64;

    // ldmatrix lane addresses
    const int arow = lane & 15, acol8 = (lane >> 4) * 8;

    for (int w = 0; w < NW; w++) {
        asm volatile("cp.async.wait_group 0;" ::: "memory");
        __syncthreads();

        __half* Wc = Ws + (w & 1) * (128 * XSH);
        if (w + 1 < NW) {
            __half* dstb = Ws + ((w + 1) & 1) * (128 * XSH);
            const __half* src = g_Wh + (size_t)(w + 1) * DD * DD;
            for (int c = tid; c < 2048; c += 256) {
                int k = c >> 4, c8 = c & 15;
                uint32_t sa = (uint32_t)__cvta_generic_to_shared(dstb + k * XSH + c8 * 8);
                cp_async16(sa, src + k * DD + c8 * 8);
            }
            asm volatile("cp.async.commit_group;" ::: "memory");
        }

        float acc[2][8][4];
#pragma unroll
        for (int mi = 0; mi < 2; mi++)
#pragma unroll
            for (int ni = 0; ni < 8; ni++)
#pragma unroll
                for (int j = 0; j < 4; j++) acc[mi][ni][j] = 0.f;

#pragma unroll
        for (int k0 = 0; k0 < 128; k0 += 16) {
            uint32_t a[2][4];
#pragma unroll
            for (int mi = 0; mi < 2; mi++) {
                uint32_t ad = (uint32_t)__cvta_generic_to_shared(
                    Xs + (m0 + mi * 16 + arow) * XSH + k0 + acol8);
                ldsm4(a[mi], ad);
            }
            uint32_t bb[4][4];
#pragma unroll
            for (int np = 0; np < 4; np++) {
                uint32_t ad = (uint32_t)__cvta_generic_to_shared(
                    Wc + (k0 + arow) * XSH + n0 + np * 16 + acol8);
                ldsm4t(bb[np], ad);
            }
#pragma unroll
            for (int mi = 0; mi < 2; mi++)
#pragma unroll
                for (int ni = 0; ni < 8; ni++)
                    mma_f16(acc[mi][ni], a[mi],
                            bb[ni >> 1][(ni & 1) * 2], bb[ni >> 1][(ni & 1) * 2 + 1]);
        }

        // epilogue
        if (w < NR) {
#pragma unroll
            for (int mi = 0; mi < 2; mi++) {
#pragma unroll
                for (int part = 0; part < 2; part++) {
                    int row = m0 + mi * 16 + (lane >> 2) + part * 8;
                    int g = row0 + row;
                    if (g < NN) {
                        __half* base = g_H + ((size_t)w * NN + g) * DD;
#pragma unroll
                        for (int ni = 0; ni < 8; ni++) {
                            int col = n0 + ni * 8 + 2 * (lane & 3);
                            *(__half2*)(base + col) =
                                __floats2half2_rn(acc[mi][ni][part * 2],
                                                  acc[mi][ni][part * 2 + 1]);
                        }
                    }
                }
            }
        } else {
#pragma unroll
            for (int mi = 0; mi < 2; mi++) {
#pragma unroll
                for (int part = 0; part < 2; part++) {
                    int row = m0 + mi * 16 + (lane >> 2) + part * 8;
                    int g = row0 + row;
                    if (g < NN) {
                        float* base = outb + (size_t)g * DD;
#pragma unroll
                        for (int ni = 0; ni < 8; ni++) {
                            int col = n0 + ni * 8 + 2 * (lane & 3);
                            float2 v;
                            v.x = acc[mi][ni][part * 2] + bs[col];
                            v.y = acc[mi][ni][part * 2 + 1] + bs[col + 1];
                            *(float2*)(base + col) = v;
                        }
                    }
                }
            }
        }
        __syncthreads();
    }
}

// ---------------------------------------------------------------------------
// CSR gather: out[d] += sum_{edges of d} scale * H[hidx]; no atomics.
// One warp per 16 dst rows; 4-deep software pipeline on H row loads.
// ---------------------------------------------------------------------------
__device__ __forceinline__ void acc_row(float4& acc, const __half* H, int h,
                                        float s, int lane) {
    uint2 raw = *(const uint2*)(H + (size_t)h * DD + lane * 4);
    __half2* hp = (__half2*)&raw;
    float2 lo = __half22float2(hp[0]);
    float2 hi = __half22float2(hp[1]);
    acc.x = fmaf(s, lo.x, acc.x);
    acc.y = fmaf(s, lo.y, acc.y);
    acc.z = fmaf(s, hi.x, acc.z);
    acc.w = fmaf(s, hi.y, acc.w);
}

__global__ void __launch_bounds__(256)
gather_kernel(float* __restrict__ out) {
    const int wid = threadIdx.x >> 5, lane = threadIdx.x & 31;
    const int dbase = blockIdx.x * 128 + wid * 16;
#pragma unroll 1
    for (int rr = 0; rr < 16; rr++) {
        int d = dbase + rr;
        if (d >= NN) return;
        float4 acc = *((float4*)(out + (size_t)d * DD) + lane);
        int e = g_rowptr[d];
        const int e1 = g_rowptr[d + 1];
        for (; e + 4 <= e1; e += 4) {
            int h0 = g_ehidx[e], h1 = g_ehidx[e + 1];
            int h2 = g_ehidx[e + 2], h3 = g_ehidx[e + 3];
            float s0 = g_escale[e], s1 = g_escale[e + 1];
            float s2 = g_escale[e + 2], s3 = g_escale[e + 3];
            acc_row(acc, g_H, h0, s0, lane);
            acc_row(acc, g_H, h1, s1, lane);
            acc_row(acc, g_H, h2, s2, lane);
            acc_row(acc, g_H, h3, s3, lane);
        }
        for (; e < e1; e++)
            acc_row(acc, g_H, g_ehidx[e], g_escale[e], lane);
        *((float4*)(out + (size_t)d * DD) + lane) = acc;
    }
}

// ---------------------------------------------------------------------------
extern "C" void kernel_launch(void* const* d_in, const int* in_sizes, int n_in,
                              void* d_out, int out_size) {
    const int*   ei     = (const int*)d_in[0];
    const int*   et     = (const int*)d_in[1];
    const float* emb    = (const float*)d_in[2];
    const float* basis1 = (const float*)d_in[3];
    const float* comp1  = (const float*)d_in[4];
    const float* root1  = (const float*)d_in[5];
    const float* bias1  = (const float*)d_in[6];
    const float* basis2 = (const float*)d_in[7];
    const float* comp2  = (const float*)d_in[8];
    const float* root2  = (const float*)d_in[9];
    const float* bias2  = (const float*)d_in[10];
    float* out = (float*)d_out;

    cudaFuncSetAttribute(gemm_h_kernel, cudaFuncAttributeMaxDynamicSharedMemorySize,
                         SMEMB);

    float* x1;
    cudaGetSymbolAddress((void**)&x1, g_x1);

    // graph preprocessing (shared by both layers)
    zero_counts_kernel<<<3125, 256>>>();
    count_kernel<<<3125, 256>>>(ei, et);
    inv_kernel<<<3125, 256>>>();
    scan1_kernel<<<NBLK, 256>>>();
    scan2_kernel<<<1, 1>>>();
    scan3_kernel<<<NBLK, 256>>>();
    fill_kernel<<<3125, 256>>>(ei, et);

    // layer 1: emb -> g_x1 (pre-activation)
    prep_wh_kernel<<<576, 256>>>(comp1, basis1, root1);
    gemm_h_kernel<<<NTILES, 256, SMEMB>>>(emb, bias1, 0, x1);
    gather_kernel<<<NTILES, 256>>>(x1);

    // layer 2: relu(g_x1) -> d_out
    prep_wh_kernel<<<576, 256>>>(comp2, basis2, root2);
    gemm_h_kernel<<<NTILES, 256, SMEMB>>>(x1, bias2, 1, out);
    gather_kernel<<<NTILES, 256>>>(out);
}

// round 5
// speedup vs baseline: 1.9533x; 1.0650x over previous
#include <cuda_runtime.h>
#include <cuda_fp16.h>
#include <cstdint>
#include <cstddef>

// Fixed problem sizes
#define NN 100000
#define NR 8
#define DD 128
#define EE 800000
#define NW 9                    // 8 relations + root
#define SEG (NN * NR)           // 800000 (dst,rel) segments
#define NTILES 782              // ceil(NN/128)
#define NBLK2 3125              // ceil(SEG/256) == ceil(EE/256)
#define XSH 136                 // smem row stride in halfs (conflict-free ldmatrix)

// ---------------------------------------------------------------------------
// Device scratch (allocation-free rule). Hot set ~65 MB -> L2-resident.
// ---------------------------------------------------------------------------
__device__ __half g_xh[(size_t)NN * DD];    // 25.6 MB: layer-1 input (emb fp16)
__device__ __half g_x1h[(size_t)NN * DD];   // 25.6 MB: relu(layer-1 out) fp16
__device__ __half g_Wh[NW * DD * DD];       // W[w][k][o] fp16, k-major
__device__ int    g_cnt[SEG];
__device__ float  g_inv[SEG];
__device__ int    g_rowptr[SEG + 1];
__device__ int    g_dpos[SEG];
__device__ int    g_bsum[NBLK2];
__device__ int    g_esrc[EE];               // src node, sorted by (dst,rel)

// ---------------------------------------------------------------------------
// PTX helpers
// ---------------------------------------------------------------------------
__device__ __forceinline__ void ldsm4(uint32_t* r, uint32_t addr) {
    asm volatile("ldmatrix.sync.aligned.m8n8.x4.shared.b16 {%0,%1,%2,%3}, [%4];"
                 : "=r"(r[0]), "=r"(r[1]), "=r"(r[2]), "=r"(r[3]) : "r"(addr));
}
__device__ __forceinline__ void ldsm4t(uint32_t* r, uint32_t addr) {
    asm volatile("ldmatrix.sync.aligned.m8n8.x4.trans.shared.b16 {%0,%1,%2,%3}, [%4];"
                 : "=r"(r[0]), "=r"(r[1]), "=r"(r[2]), "=r"(r[3]) : "r"(addr));
}
__device__ __forceinline__ void mma_f16(float* d, const uint32_t* a, uint32_t b0, uint32_t b1) {
    asm volatile(
        "mma.sync.aligned.m16n8k16.row.col.f32.f16.f16.f32 "
        "{%0,%1,%2,%3}, {%4,%5,%6,%7}, {%8,%9}, {%0,%1,%2,%3};"
        : "+f"(d[0]), "+f"(d[1]), "+f"(d[2]), "+f"(d[3])
        : "r"(a[0]), "r"(a[1]), "r"(a[2]), "r"(a[3]), "r"(b0), "r"(b1));
}
__device__ __forceinline__ void cp_async16(uint32_t smem_addr, const void* gptr) {
    asm volatile("cp.async.cg.shared.global [%0], [%1], 16;" :: "r"(smem_addr), "l"(gptr));
}

// ---------------------------------------------------------------------------
// Graph preprocessing: CSR over (dst*8 + rel) segments, built once per call
// ---------------------------------------------------------------------------
__global__ void zero_cnt_kernel() {
    int i = blockIdx.x * blockDim.x + threadIdx.x;
    if (i < SEG) g_cnt[i] = 0;
}

__global__ void count_kernel(const int* __restrict__ ei, const int* __restrict__ et) {
    int e = blockIdx.x * blockDim.x + threadIdx.x;
    if (e < EE) atomicAdd(&g_cnt[ei[EE + e] * NR + et[e]], 1);
}

__global__ void inv_kernel() {
    int i = blockIdx.x * blockDim.x + threadIdx.x;
    if (i < SEG) g_inv[i] = 1.0f / fmaxf((float)g_cnt[i], 1.0f);
}

__global__ void scan1_kernel() {   // per-256-chunk sums of g_cnt
    __shared__ int sc[256];
    int i = blockIdx.x * 256 + threadIdx.x;
    sc[threadIdx.x] = (i < SEG) ? g_cnt[i] : 0;
    __syncthreads();
    for (int off = 128; off > 0; off >>= 1) {
        if (threadIdx.x < off) sc[threadIdx.x] += sc[threadIdx.x + off];
        __syncthreads();
    }
    if (threadIdx.x == 0) g_bsum[blockIdx.x] = sc[0];
}

__global__ void scan2_kernel() {   // parallel exclusive scan over g_bsum[NBLK2]
    __shared__ int sm[1024];
    __shared__ int carry;
    int tid = threadIdx.x;
    if (tid == 0) carry = 0;
    __syncthreads();
    for (int base = 0; base < NBLK2; base += 1024) {
        int i = base + tid;
        int v = (i < NBLK2) ? g_bsum[i] : 0;
        sm[tid] = v;
        __syncthreads();
        for (int off = 1; off < 1024; off <<= 1) {
            int t = (tid >= off) ? sm[tid - off] : 0;
            __syncthreads();
            sm[tid] += t;
            __syncthreads();
        }
        int incl = sm[tid];
        if (i < NBLK2) g_bsum[i] = carry + incl - v;   // exclusive
        __syncthreads();
        if (tid == 0) carry += sm[1023];
        __syncthreads();
    }
    if (tid == 0) g_rowptr[SEG] = EE;
}

__global__ void scan3_kernel() {   // rowptr = global exclusive prefix of cnt
    __shared__ int sc[256];
    int i = blockIdx.x * 256 + threadIdx.x;
    int c = (i < SEG) ? g_cnt[i] : 0;
    sc[threadIdx.x] = c;
    __syncthreads();
    for (int off = 1; off < 256; off <<= 1) {
        int v = (threadIdx.x >= off) ? sc[threadIdx.x - off] : 0;
        __syncthreads();
        sc[threadIdx.x] += v;
        __syncthreads();
    }
    if (i < SEG) {
        int rp = g_bsum[blockIdx.x] + sc[threadIdx.x] - c;
        g_rowptr[i] = rp;
        g_dpos[i] = rp;
    }
}

__global__ void fill_kernel(const int* __restrict__ ei, const int* __restrict__ et) {
    int e = blockIdx.x * blockDim.x + threadIdx.x;
    if (e >= EE) return;
    int seg = ei[EE + e] * NR + et[e];
    int pos = atomicAdd(&g_dpos[seg], 1);
    g_esrc[pos] = ei[e];
}

__global__ void conv_emb_kernel(const float* __restrict__ emb) {
    int i = blockIdx.x * blockDim.x + threadIdx.x;   // over 3.2M float4
    if (i >= NN * DD / 4) return;
    float4 v = *((const float4*)emb + i);
    __half2* p = (__half2*)(g_xh + (size_t)i * 4);
    p[0] = __floats2half2_rn(v.x, v.y);
    p[1] = __floats2half2_rn(v.z, v.w);
}

// weight prep: g_Wh[w][k][o] fp16 (k-major)
__global__ void prep_wh_kernel(const float* __restrict__ comp,
                               const float* __restrict__ basis,
                               const float* __restrict__ root) {
    int idx = blockIdx.x * blockDim.x + threadIdx.x;
    if (idx >= NW * DD * DD) return;
    int w = idx >> 14;
    int rem = idx & 16383;
    int k = rem >> 7, o = rem & 127;
    float v;
    if (w < NR) {
        v = 0.f;
#pragma unroll
        for (int b = 0; b < 8; b++)
            v += comp[w * 8 + b] * basis[((size_t)b * DD + k) * DD + o];
    } else {
        v = root[k * DD + o];
    }
    g_Wh[idx] = __float2half_rn(v);
}

// ---------------------------------------------------------------------------
// Fused kernel: per 128-dst tile, for each relation build the mean-agg A-tile
// in smem (quarter-warp gather from L2-resident Xsrc), MMA against W_r;
// root K-block uses contiguous Xsrc rows. Single output write at the end.
// ---------------------------------------------------------------------------
#define SMEMB (3 * 128 * XSH * 2 + 512)

__global__ void __launch_bounds__(256, 2)
fused_kernel(const __half* __restrict__ Xsrc, const float* __restrict__ bias,
             float* __restrict__ out32, __half* __restrict__ outh) {
    extern __shared__ __half smh[];
    __half* As = smh;                      // [128][XSH]
    __half* Ws = smh + 128 * XSH;          // 2 buffers [128][XSH]
    float* bs = (float*)(smh + 3 * 128 * XSH);

    const int tid = threadIdx.x;
    const int wid = tid >> 5, lane = tid & 31;
    const int row0 = blockIdx.x * 128;
    if (tid < 128) bs[tid] = bias[tid];

    // prefetch W[0]
    for (int c = tid; c < 2048; c += 256) {
        int k = c >> 4, c8 = c & 15;
        uint32_t sa = (uint32_t)__cvta_generic_to_shared(Ws + k * XSH + c8 * 8);
        cp_async16(sa, g_Wh + k * DD + c8 * 8);
    }
    asm volatile("cp.async.commit_group;" ::: "memory");

    const int m0 = (wid >> 1) * 32, n0 = (wid & 1) * 64;
    const int arow = lane & 15, acol8 = (lane >> 4) * 8;
    const int sub = lane >> 3, sl = lane & 7;   // quarter-warp: 8 lanes/segment

    float acc[2][8][4];
#pragma unroll
    for (int mi = 0; mi < 2; mi++)
#pragma unroll
        for (int ni = 0; ni < 8; ni++)
#pragma unroll
            for (int j = 0; j < 4; j++) acc[mi][ni][j] = 0.f;

    for (int w = 0; w < NW; w++) {
        // ---- stage A-tile ----
        if (w < NR) {
            // mean-aggregation gather: 4 segments in flight per warp
#pragma unroll 1
            for (int g4 = 0; g4 < 4; g4++) {
                int row = wid * 16 + g4 * 4 + sub;
                int dst = row0 + row;
                float af[16];
#pragma unroll
                for (int j = 0; j < 16; j++) af[j] = 0.f;
                float s = 0.f;
                if (dst < NN) {
                    int seg = dst * NR + w;
                    int e = g_rowptr[seg];
                    int e1 = g_rowptr[seg + 1];
                    s = g_inv[seg];
                    for (; e < e1; e++) {
                        int src = g_esrc[e];
                        const uint4* p = (const uint4*)(Xsrc + (size_t)src * DD) + sl * 2;
                        uint4 q0 = p[0], q1 = p[1];
                        const __half2* h0 = (const __half2*)&q0;
                        const __half2* h1 = (const __half2*)&q1;
#pragma unroll
                        for (int j = 0; j < 4; j++) {
                            float2 f0 = __half22float2(h0[j]);
                            af[j * 2]     += f0.x;
                            af[j * 2 + 1] += f0.y;
                            float2 f1 = __half22float2(h1[j]);
                            af[8 + j * 2]     += f1.x;
                            af[8 + j * 2 + 1] += f1.y;
                        }
                    }
                }
                uint4 st0, st1;
                __half2* o0 = (__half2*)&st0;
                __half2* o1 = (__half2*)&st1;
#pragma unroll
                for (int j = 0; j < 4; j++) {
                    o0[j] = __floats2half2_rn(af[j * 2] * s, af[j * 2 + 1] * s);
                    o1[j] = __floats2half2_rn(af[8 + j * 2] * s, af[8 + j * 2 + 1] * s);
                }
                *(uint4*)(As + row * XSH + sl * 16) = st0;
                *(uint4*)(As + row * XSH + sl * 16 + 8) = st1;
            }
        } else {
            // root block: contiguous Xsrc rows of this tile
            for (int c = tid; c < 2048; c += 256) {
                int r = c >> 4, c8 = c & 15;
                int g = row0 + r;
                uint4 v = make_uint4(0u, 0u, 0u, 0u);
                if (g < NN) v = *((const uint4*)(Xsrc + (size_t)g * DD) + c8);
                *(uint4*)(As + r * XSH + c8 * 8) = v;
            }
        }

        // ---- prefetch next W, wait for current ----
        if (w + 1 < NW) {
            const __half* srcW = g_Wh + (size_t)(w + 1) * DD * DD;
            __half* dstb = Ws + ((w + 1) & 1) * (128 * XSH);
            for (int c = tid; c < 2048; c += 256) {
                int k = c >> 4, c8 = c & 15;
                uint32_t sa = (uint32_t)__cvta_generic_to_shared(dstb + k * XSH + c8 * 8);
                cp_async16(sa, srcW + k * DD + c8 * 8);
            }
            asm volatile("cp.async.commit_group;" ::: "memory");
            asm volatile("cp.async.wait_group 1;" ::: "memory");
        } else {
            asm volatile("cp.async.wait_group 0;" ::: "memory");
        }
        __syncthreads();

        // ---- MMA K-block (K=128) ----
        __half* Wc = Ws + (w & 1) * (128 * XSH);
#pragma unroll
        for (int k0 = 0; k0 < 128; k0 += 16) {
            uint32_t a[2][4];
#pragma unroll
            for (int mi = 0; mi < 2; mi++) {
                uint32_t ad = (uint32_t)__cvta_generic_to_shared(
                    As + (m0 + mi * 16 + arow) * XSH + k0 + acol8);
                ldsm4(a[mi], ad);
            }
            uint32_t bb[4][4];
#pragma unroll
            for (int np = 0; np < 4; np++) {
                uint32_t ad = (uint32_t)__cvta_generic_to_shared(
                    Wc + (k0 + arow) * XSH + n0 + np * 16 + acol8);
                ldsm4t(bb[np], ad);
            }
#pragma unroll
            for (int mi = 0; mi < 2; mi++)
#pragma unroll
                for (int ni = 0; ni < 8; ni++)
                    mma_f16(acc[mi][ni], a[mi],
                            bb[ni >> 1][(ni & 1) * 2], bb[ni >> 1][(ni & 1) * 2 + 1]);
        }
        __syncthreads();   // done reading As/W before next overwrite
    }

    // ---- epilogue: single output write ----
#pragma unroll
    for (int mi = 0; mi < 2; mi++) {
#pragma unroll
        for (int part = 0; part < 2; part++) {
            int row = m0 + mi * 16 + (lane >> 2) + part * 8;
            int g = row0 + row;
            if (g < NN) {
                if (out32) {
                    float* base = out32 + (size_t)g * DD;
#pragma unroll
                    for (int ni = 0; ni < 8; ni++) {
                        int col = n0 + ni * 8 + 2 * (lane & 3);
                        float2 v;
                        v.x = acc[mi][ni][part * 2]     + bs[col];
                        v.y = acc[mi][ni][part * 2 + 1] + bs[col + 1];
                        *(float2*)(base + col) = v;
                    }
                } else {
                    __half* base = outh + (size_t)g * DD;
#pragma unroll
                    for (int ni = 0; ni < 8; ni++) {
                        int col = n0 + ni * 8 + 2 * (lane & 3);
                        float vx = fmaxf(acc[mi][ni][part * 2]     + bs[col], 0.f);
                        float vy = fmaxf(acc[mi][ni][part * 2 + 1] + bs[col + 1], 0.f);
                        *(__half2*)(base + col) = __floats2half2_rn(vx, vy);
                    }
                }
            }
        }
    }
}

// ---------------------------------------------------------------------------
extern "C" void kernel_launch(void* const* d_in, const int* in_sizes, int n_in,
                              void* d_out, int out_size) {
    const int*   ei     = (const int*)d_in[0];
    const int*   et     = (const int*)d_in[1];
    const float* emb    = (const float*)d_in[2];
    const float* basis1 = (const float*)d_in[3];
    const float* comp1  = (const float*)d_in[4];
    const float* root1  = (const float*)d_in[5];
    const float* bias1  = (const float*)d_in[6];
    const float* basis2 = (const float*)d_in[7];
    const float* comp2  = (const float*)d_in[8];
    const float* root2  = (const float*)d_in[9];
    const float* bias2  = (const float*)d_in[10];
    float* out = (float*)d_out;

    cudaFuncSetAttribute(fused_kernel, cudaFuncAttributeMaxDynamicSharedMemorySize,
                         SMEMB);

    __half *xh, *x1h;
    cudaGetSymbolAddress((void**)&xh, g_xh);
    cudaGetSymbolAddress((void**)&x1h, g_x1h);

    // preprocessing (segment CSR shared by both layers)
    zero_cnt_kernel<<<NBLK2, 256>>>();
    count_kernel<<<NBLK2, 256>>>(ei, et);
    inv_kernel<<<NBLK2, 256>>>();
    scan1_kernel<<<NBLK2, 256>>>();
    scan2_kernel<<<1, 1024>>>();
    scan3_kernel<<<NBLK2, 256>>>();
    fill_kernel<<<NBLK2, 256>>>(ei, et);
    conv_emb_kernel<<<12500, 256>>>(emb);

    // layer 1: g_xh -> relu -> g_x1h (fp16)
    prep_wh_kernel<<<576, 256>>>(comp1, basis1, root1);
    fused_kernel<<<NTILES, 256, SMEMB>>>(xh, bias1, nullptr, x1h);

    // layer 2: g_x1h -> out (fp32, +bias)
    prep_wh_kernel<<<576, 256>>>(comp2, basis2, root2);
    fused_kernel<<<NTILES, 256, SMEMB>>>(x1h, bias2, out, nullptr);
}